// round 1
// baseline (speedup 1.0000x reference)
#include <cuda_runtime.h>
#include <math.h>
#include <stdint.h>

// ---------------------------------------------------------------------------
// Problem constants
// ---------------------------------------------------------------------------
#define N_NODES 50000
#define N_EDGES 10000
#define NNZ     400000
#define QDIM    128
#define VDIM    256
#define EDIM    256
#define KIN     256
#define NEG_SLOPE 0.01f
// 1/sqrt(QDIM) = 1/sqrt(128)
#define SCORE_SCALE 0.08838834764831845f

// ---------------------------------------------------------------------------
// Static scratch (no allocation allowed)
// ---------------------------------------------------------------------------
__device__ float g_feat_v[N_NODES * VDIM];   // 51.2 MB
__device__ float g_k1[N_NODES * QDIM];       // 25.6 MB
__device__ float g_v1[N_NODES * EDIM];       // 51.2 MB
__device__ float g_q2[N_NODES * QDIM];       // 25.6 MB
__device__ float g_q1[N_EDGES * QDIM];       // 5.1 MB
__device__ float g_k2[N_EDGES * QDIM];       // 5.1 MB
__device__ float g_v2[N_EDGES * VDIM];       // 10.2 MB
__device__ float g_score[NNZ];
__device__ float g_expw[NNZ];
__device__ float g_segmax[N_NODES];
__device__ float g_segsum[N_NODES];
__device__ int   g_counts[N_NODES];
__device__ int   g_offsets[N_NODES + 1];
__device__ int   g_cursor[N_NODES];
__device__ int   g_perm[NNZ];

// ---------------------------------------------------------------------------
// SGEMM: C[M,N] = A[M,K] @ W[N,K]^T + bias[N]   (fp32, float4 vectorized)
// BM=128, BN=64, BK=16, TM=8, TN=4, 256 threads
// Requires: N % 64 == 0, K % 16 == 0 (true for all calls here). M guarded.
// ---------------------------------------------------------------------------
#define BM 128
#define BN 64
#define BK 16
#define TM 8
#define TN 4

__global__ __launch_bounds__(256) void sgemm_bias_kernel(
    const float* __restrict__ A, const float* __restrict__ W,
    const float* __restrict__ bias, float* __restrict__ C,
    int M, int N, int K)
{
    __shared__ float As[BK][BM + 4];
    __shared__ float Bs[BK][BN + 4];

    const int tid = threadIdx.x;
    const int block_m = blockIdx.y * BM;
    const int block_n = blockIdx.x * BN;

    const int tx = tid & 15;   // n direction (16)
    const int ty = tid >> 4;   // m direction (16)

    // load mapping
    const int a_row  = tid >> 2;        // 0..63
    const int a_col4 = (tid & 3) * 4;   // 0,4,8,12
    const int w_row  = tid >> 2;        // 0..63
    const int w_col4 = (tid & 3) * 4;

    float acc[TM][TN];
#pragma unroll
    for (int i = 0; i < TM; i++)
#pragma unroll
        for (int j = 0; j < TN; j++) acc[i][j] = 0.f;

    for (int k0 = 0; k0 < K; k0 += BK) {
        // --- load A tile (128 x 16), transposed into As[k][m] ---
#pragma unroll
        for (int r = 0; r < 2; r++) {
            const int m = a_row + r * 64;
            float4 v = make_float4(0.f, 0.f, 0.f, 0.f);
            const int gm = block_m + m;
            if (gm < M)
                v = *(const float4*)&A[(size_t)gm * K + k0 + a_col4];
            As[a_col4 + 0][m] = v.x;
            As[a_col4 + 1][m] = v.y;
            As[a_col4 + 2][m] = v.z;
            As[a_col4 + 3][m] = v.w;
        }
        // --- load W tile (64 x 16), transposed into Bs[k][n] ---
        {
            float4 v = *(const float4*)&W[(size_t)(block_n + w_row) * K + k0 + w_col4];
            Bs[w_col4 + 0][w_row] = v.x;
            Bs[w_col4 + 1][w_row] = v.y;
            Bs[w_col4 + 2][w_row] = v.z;
            Bs[w_col4 + 3][w_row] = v.w;
        }
        __syncthreads();

#pragma unroll
        for (int k = 0; k < BK; k++) {
            float4 ra0 = *(const float4*)&As[k][ty * TM + 0];
            float4 ra1 = *(const float4*)&As[k][ty * TM + 4];
            float4 rb  = *(const float4*)&Bs[k][tx * TN];
            const float ram[TM] = {ra0.x, ra0.y, ra0.z, ra0.w, ra1.x, ra1.y, ra1.z, ra1.w};
            const float rbn[TN] = {rb.x, rb.y, rb.z, rb.w};
#pragma unroll
            for (int i = 0; i < TM; i++)
#pragma unroll
                for (int j = 0; j < TN; j++) acc[i][j] += ram[i] * rbn[j];
        }
        __syncthreads();
    }

    // epilogue
#pragma unroll
    for (int i = 0; i < TM; i++) {
        const int m = block_m + ty * TM + i;
        if (m < M) {
#pragma unroll
            for (int j = 0; j < TN; j++) {
                const int n = block_n + tx * TN + j;
                C[(size_t)m * N + n] = acc[i][j] + bias[n];
            }
        }
    }
}

static void run_gemm(const float* A, const float* W, const float* b, float* C,
                     int M, int N, int K)
{
    dim3 grid(N / BN, (M + BM - 1) / BM);
    sgemm_bias_kernel<<<grid, 256>>>(A, W, b, C, M, N, K);
}

// ---------------------------------------------------------------------------
// Softmax / segment machinery
// ---------------------------------------------------------------------------
__device__ __forceinline__ void atomicMaxFloat(float* addr, float val)
{
    // Ordered-int trick. Works for any mix given init = -inf.
    if (val >= 0.f)
        atomicMax((int*)addr, __float_as_int(val));
    else
        atomicMin((unsigned int*)addr, __float_as_uint(val));
}

__global__ void init_pass_kernel(float* segmax, float* segsum, int* counts, int nseg)
{
    int i = blockIdx.x * blockDim.x + threadIdx.x;
    if (i < nseg) {
        segmax[i] = -INFINITY;
        segsum[i] = 0.f;
        counts[i] = 0;
    }
}

// One warp per nnz: score = leaky_relu(dot(kmat[kidx], qmat[qidx])) * scale.
// Also accumulates segment max and segment histogram.
__global__ __launch_bounds__(256) void score_kernel(
    const float* __restrict__ kmat, const float* __restrict__ qmat,
    const int* __restrict__ kidx, const int* __restrict__ qidx,
    const int* __restrict__ seg,
    float* __restrict__ score, float* __restrict__ segmax, int* __restrict__ counts,
    int nnz)
{
    const int w = (blockIdx.x * blockDim.x + threadIdx.x) >> 5;
    const int lane = threadIdx.x & 31;
    if (w >= nnz) return;
    const int ki = kidx[w];
    const int qi = qidx[w];
    float4 a = *(const float4*)&kmat[(size_t)ki * QDIM + lane * 4];
    float4 b = *(const float4*)&qmat[(size_t)qi * QDIM + lane * 4];
    float d = a.x * b.x + a.y * b.y + a.z * b.z + a.w * b.w;
#pragma unroll
    for (int o = 16; o > 0; o >>= 1) d += __shfl_xor_sync(0xffffffffu, d, o);
    if (lane == 0) {
        float s = (d >= 0.f ? d : NEG_SLOPE * d) * SCORE_SCALE;
        score[w] = s;
        const int sg = seg[w];
        atomicMaxFloat(&segmax[sg], s);
        atomicAdd(&counts[sg], 1);
    }
}

// Single-block exclusive scan: counts[0..n) -> offsets[0..n], cursor = offsets copy
__global__ void scan_kernel(const int* __restrict__ counts, int* __restrict__ offsets,
                            int* __restrict__ cursor, int n)
{
    __shared__ int sh[1024];
    __shared__ int carry;
    const int t = threadIdx.x;
    if (t == 0) carry = 0;
    __syncthreads();
    for (int base = 0; base < n; base += 1024) {
        const int i = base + t;
        const int x = (i < n) ? counts[i] : 0;
        sh[t] = x;
        __syncthreads();
        for (int off = 1; off < 1024; off <<= 1) {
            int v = (t >= off) ? sh[t - off] : 0;
            __syncthreads();
            sh[t] += v;
            __syncthreads();
        }
        const int excl = carry + sh[t] - x;
        if (i < n) {
            offsets[i] = excl;
            cursor[i] = excl;
        }
        __syncthreads();
        if (t == 1023) carry += sh[1023];
        __syncthreads();
    }
    if (t == 0) offsets[n] = carry;
}

__global__ void build_perm_kernel(const int* __restrict__ seg, int* __restrict__ cursor,
                                  int* __restrict__ perm, int nnz)
{
    int i = blockIdx.x * blockDim.x + threadIdx.x;
    if (i < nnz) {
        int pos = atomicAdd(&cursor[seg[i]], 1);
        perm[pos] = i;
    }
}

__global__ void expsum_kernel(const float* __restrict__ score, const int* __restrict__ seg,
                              const float* __restrict__ segmax, float* __restrict__ expw,
                              float* __restrict__ segsum, int nnz)
{
    int i = blockIdx.x * blockDim.x + threadIdx.x;
    if (i < nnz) {
        const int sg = seg[i];
        float e = expf(score[i] - segmax[sg]);
        expw[i] = e;
        atomicAdd(&segsum[sg], e);
    }
}

// One block (256 threads = 256 dims) per segment. CSR gather with staged
// indices in shared memory so vmat row loads are independent (high MLP).
__global__ __launch_bounds__(256) void aggregate_kernel(
    const float* __restrict__ vmat,      // [*, 256]
    const int* __restrict__ rowidx,      // per-nnz source row
    const int* __restrict__ offsets, const int* __restrict__ perm,
    const float* __restrict__ expw, const float* __restrict__ segsum,
    float* __restrict__ out, int nseg)
{
    __shared__ int   sh_r[128];
    __shared__ float sh_w[128];
    const int s = blockIdx.x;
    if (s >= nseg) return;
    const int d = threadIdx.x;
    const int beg = offsets[s];
    const int end = offsets[s + 1];
    float acc = 0.f;
    for (int cb = beg; cb < end; cb += 128) {
        const int m = min(128, end - cb);
        if (d < m) {
            const int nz = perm[cb + d];
            sh_w[d] = expw[nz];
            sh_r[d] = rowidx[nz];
        }
        __syncthreads();
        for (int j = 0; j < m; j++)
            acc += sh_w[j] * vmat[(size_t)sh_r[j] * 256 + d];
        __syncthreads();
    }
    const float denom = fmaxf(segsum[s], 1e-20f);
    out[(size_t)s * 256 + d] = fmaxf(acc / denom, 0.f);  // relu
}

// ---------------------------------------------------------------------------
// Launch
// ---------------------------------------------------------------------------
extern "C" void kernel_launch(void* const* d_in, const int* in_sizes, int n_in,
                              void* d_out, int out_size)
{
    const float* vfeat    = (const float*)d_in[0];
    const float* efeat    = (const float*)d_in[1];
    const int*   node_idx = (const int*)d_in[2];
    const int*   edge_idx = (const int*)d_in[3];
    const float* W_vtx = (const float*)d_in[4];  const float* b_vtx = (const float*)d_in[5];
    const float* W_qe  = (const float*)d_in[6];  const float* b_qe  = (const float*)d_in[7];
    const float* W_kv  = (const float*)d_in[8];  const float* b_kv  = (const float*)d_in[9];
    const float* W_vv  = (const float*)d_in[10]; const float* b_vv  = (const float*)d_in[11];
    const float* W_qv  = (const float*)d_in[12]; const float* b_qv  = (const float*)d_in[13];
    const float* W_ke  = (const float*)d_in[14]; const float* b_ke  = (const float*)d_in[15];
    const float* W_ve  = (const float*)d_in[16]; const float* b_ve  = (const float*)d_in[17];

    float* out_v = (float*)d_out;                       // [N_NODES, VDIM]
    float* out_e = out_v + (size_t)N_NODES * VDIM;      // [N_EDGES, EDIM]

    float *feat_v, *k1, *v1, *q2, *q1, *k2, *v2, *score, *expw, *segmax, *segsum;
    int *counts, *offsets, *cursor, *perm;
    cudaGetSymbolAddress((void**)&feat_v, g_feat_v);
    cudaGetSymbolAddress((void**)&k1, g_k1);
    cudaGetSymbolAddress((void**)&v1, g_v1);
    cudaGetSymbolAddress((void**)&q2, g_q2);
    cudaGetSymbolAddress((void**)&q1, g_q1);
    cudaGetSymbolAddress((void**)&k2, g_k2);
    cudaGetSymbolAddress((void**)&v2, g_v2);
    cudaGetSymbolAddress((void**)&score, g_score);
    cudaGetSymbolAddress((void**)&expw, g_expw);
    cudaGetSymbolAddress((void**)&segmax, g_segmax);
    cudaGetSymbolAddress((void**)&segsum, g_segsum);
    cudaGetSymbolAddress((void**)&counts, g_counts);
    cudaGetSymbolAddress((void**)&offsets, g_offsets);
    cudaGetSymbolAddress((void**)&cursor, g_cursor);
    cudaGetSymbolAddress((void**)&perm, g_perm);

    const int scoreBlocks = (NNZ * 32 + 255) / 256;   // one warp per nnz
    const int nnzBlocks   = (NNZ + 255) / 256;

    // ---- node-side and edge-side projections ----
    run_gemm(vfeat,  W_vtx, b_vtx, feat_v, N_NODES, VDIM, KIN);   // feat_v
    run_gemm(feat_v, W_kv,  b_kv,  k1,     N_NODES, QDIM, VDIM);  // k1
    run_gemm(feat_v, W_vv,  b_vv,  v1,     N_NODES, EDIM, VDIM);  // v1
    run_gemm(feat_v, W_qv,  b_qv,  q2,     N_NODES, QDIM, VDIM);  // q2
    run_gemm(efeat,  W_qe,  b_qe,  q1,     N_EDGES, QDIM, KIN);   // q1

    // ---- pass 1: nodes -> hyperedges (segments = edge_idx, nseg = N_EDGES) ----
    init_pass_kernel<<<(N_EDGES + 255) / 256, 256>>>(segmax, segsum, counts, N_EDGES);
    score_kernel<<<scoreBlocks, 256>>>(k1, q1, node_idx, edge_idx, edge_idx,
                                       score, segmax, counts, NNZ);
    scan_kernel<<<1, 1024>>>(counts, offsets, cursor, N_EDGES);
    build_perm_kernel<<<nnzBlocks, 256>>>(edge_idx, cursor, perm, NNZ);
    expsum_kernel<<<nnzBlocks, 256>>>(score, edge_idx, segmax, expw, segsum, NNZ);
    aggregate_kernel<<<N_EDGES, 256>>>(v1, node_idx, offsets, perm, expw, segsum,
                                       out_e, N_EDGES);   // feat_e (output 2)

    // ---- edge-side projections from feat_e ----
    run_gemm(out_e, W_ke, b_ke, k2, N_EDGES, QDIM, EDIM);
    run_gemm(out_e, W_ve, b_ve, v2, N_EDGES, VDIM, EDIM);

    // ---- pass 2: hyperedges -> nodes (segments = node_idx, nseg = N_NODES) ----
    init_pass_kernel<<<(N_NODES + 255) / 256, 256>>>(segmax, segsum, counts, N_NODES);
    score_kernel<<<scoreBlocks, 256>>>(k2, q2, edge_idx, node_idx, node_idx,
                                       score, segmax, counts, NNZ);
    scan_kernel<<<1, 1024>>>(counts, offsets, cursor, N_NODES);
    build_perm_kernel<<<nnzBlocks, 256>>>(node_idx, cursor, perm, NNZ);
    expsum_kernel<<<nnzBlocks, 256>>>(score, node_idx, segmax, expw, segsum, NNZ);
    aggregate_kernel<<<N_NODES, 256>>>(v2, edge_idx, offsets, perm, expw, segsum,
                                       out_v, N_NODES);   // feat_v_out (output 1)
}

// round 2
// speedup vs baseline: 1.0101x; 1.0101x over previous
#include <cuda_runtime.h>
#include <math.h>
#include <stdint.h>

// ---------------------------------------------------------------------------
// Problem constants
// ---------------------------------------------------------------------------
#define N_NODES 50000
#define N_EDGES 10000
#define NNZ     400000
#define QDIM    128
#define VDIM    256
#define EDIM    256
#define KIN     256
#define NEG_SLOPE 0.01f
#define SCORE_SCALE 0.08838834764831845f   // 1/sqrt(128)

// ---------------------------------------------------------------------------
// Static scratch (no allocation allowed)
// ---------------------------------------------------------------------------
__device__ float g_feat_v[N_NODES * VDIM];
__device__ float g_k1[N_NODES * QDIM];
__device__ float g_v1[N_NODES * EDIM];
__device__ float g_q2[N_NODES * QDIM];
__device__ float g_q1[N_EDGES * QDIM];
__device__ float g_k2[N_EDGES * QDIM];
__device__ float g_v2[N_EDGES * VDIM];
__device__ float g_score[NNZ];
__device__ float g_expw[NNZ];
__device__ float g_segmax[N_NODES];
__device__ float g_segsum[N_NODES];
__device__ int   g_counts[N_NODES];
__device__ int   g_offsets[N_NODES + 1];
__device__ int   g_cursor[N_NODES];
__device__ int   g_perm[NNZ];
__device__ int   g_partials[64];

// ---------------------------------------------------------------------------
// 3xTF32 tensor-core GEMM: C[M,N] = A[M,K] @ W[N,K]^T + bias[N]
// Accuracy ~fp32 (error O(2^-22)): x = hi + lo (both tf32), compute
// hi*hi + hi*lo + lo*hi on tensor cores, accumulate fp32.
// BM=128, BN=64, BK=16, 256 threads (8 warps as 4m x 2n, warp tile 32x32).
// Requires N % 64 == 0, K % 16 == 0 (true for all calls). M guarded.
// ---------------------------------------------------------------------------
#define BM 128
#define BN 64
#define BK 16
#define SSTR 20   // BK + 4 pad: bank = (row*20 + col) % 32 is conflict-free

__device__ __forceinline__ uint32_t f2tf(float x)
{
    uint32_t r;
    asm("cvt.rna.tf32.f32 %0, %1;" : "=r"(r) : "f"(x));
    return r;
}

__device__ __forceinline__ void mma_tf32(float* c, const uint32_t* a, const uint32_t* b)
{
    asm volatile(
        "mma.sync.aligned.m16n8k8.row.col.f32.tf32.tf32.f32 "
        "{%0,%1,%2,%3}, {%4,%5,%6,%7}, {%8,%9}, {%0,%1,%2,%3};"
        : "+f"(c[0]), "+f"(c[1]), "+f"(c[2]), "+f"(c[3])
        : "r"(a[0]), "r"(a[1]), "r"(a[2]), "r"(a[3]), "r"(b[0]), "r"(b[1]));
}

__global__ __launch_bounds__(256) void gemm_tf32_kernel(
    const float* __restrict__ A, const float* __restrict__ W,
    const float* __restrict__ bias, float* __restrict__ C,
    int M, int N, int K)
{
    __shared__ uint32_t As_hi[BM][SSTR];
    __shared__ uint32_t As_lo[BM][SSTR];
    __shared__ uint32_t Bs_hi[BN][SSTR];
    __shared__ uint32_t Bs_lo[BN][SSTR];

    const int tid  = threadIdx.x;
    const int lane = tid & 31;
    const int wid  = tid >> 5;
    const int wm   = wid & 3;   // warp m index (0..3), 32 rows each
    const int wn   = wid >> 2;  // warp n index (0..1), 32 cols each
    const int g    = lane >> 2; // group (0..7)
    const int t4   = lane & 3;

    const int block_m = blockIdx.y * BM;
    const int block_n = blockIdx.x * BN;

    // staging maps
    const int ar = tid >> 1;           // A row 0..127
    const int ac = (tid & 1) * 8;      // 8 floats (2 float4)
    const int br = tid >> 2;           // W row 0..63
    const int bc = (tid & 3) * 4;      // 4 floats (1 float4)

    float acc[2][4][4];
#pragma unroll
    for (int i = 0; i < 2; i++)
#pragma unroll
        for (int j = 0; j < 4; j++)
#pragma unroll
            for (int l = 0; l < 4; l++) acc[i][j][l] = 0.f;

    for (int k0 = 0; k0 < K; k0 += BK) {
        // ---- stage A (128 x 16) with hi/lo split ----
        {
            const int gm = block_m + ar;
#pragma unroll
            for (int u = 0; u < 2; u++) {
                float4 v = make_float4(0.f, 0.f, 0.f, 0.f);
                if (gm < M) v = *(const float4*)&A[(size_t)gm * K + k0 + ac + u * 4];
                const float vv[4] = {v.x, v.y, v.z, v.w};
#pragma unroll
                for (int j = 0; j < 4; j++) {
                    const int c = ac + u * 4 + j;
                    uint32_t h = f2tf(vv[j]);
                    As_hi[ar][c] = h;
                    As_lo[ar][c] = f2tf(vv[j] - __uint_as_float(h));
                }
            }
        }
        // ---- stage W (64 x 16) ----
        {
            float4 v = *(const float4*)&W[(size_t)(block_n + br) * K + k0 + bc];
            const float vv[4] = {v.x, v.y, v.z, v.w};
#pragma unroll
            for (int j = 0; j < 4; j++) {
                uint32_t h = f2tf(vv[j]);
                Bs_hi[br][bc + j] = h;
                Bs_lo[br][bc + j] = f2tf(vv[j] - __uint_as_float(h));
            }
        }
        __syncthreads();

#pragma unroll
        for (int kk = 0; kk < BK; kk += 8) {
            uint32_t ahi[2][4], alo[2][4];
#pragma unroll
            for (int mt = 0; mt < 2; mt++) {
                const int m0 = wm * 32 + mt * 16 + g;
                ahi[mt][0] = As_hi[m0][kk + t4];
                ahi[mt][1] = As_hi[m0 + 8][kk + t4];
                ahi[mt][2] = As_hi[m0][kk + t4 + 4];
                ahi[mt][3] = As_hi[m0 + 8][kk + t4 + 4];
                alo[mt][0] = As_lo[m0][kk + t4];
                alo[mt][1] = As_lo[m0 + 8][kk + t4];
                alo[mt][2] = As_lo[m0][kk + t4 + 4];
                alo[mt][3] = As_lo[m0 + 8][kk + t4 + 4];
            }
            uint32_t bhi[4][2], blo[4][2];
#pragma unroll
            for (int nt = 0; nt < 4; nt++) {
                const int n0 = wn * 32 + nt * 8 + g;
                bhi[nt][0] = Bs_hi[n0][kk + t4];
                bhi[nt][1] = Bs_hi[n0][kk + t4 + 4];
                blo[nt][0] = Bs_lo[n0][kk + t4];
                blo[nt][1] = Bs_lo[n0][kk + t4 + 4];
            }
#pragma unroll
            for (int mt = 0; mt < 2; mt++)
#pragma unroll
                for (int nt = 0; nt < 4; nt++) {
                    mma_tf32(acc[mt][nt], ahi[mt], bhi[nt]);
                    mma_tf32(acc[mt][nt], ahi[mt], blo[nt]);
                    mma_tf32(acc[mt][nt], alo[mt], bhi[nt]);
                }
        }
        __syncthreads();
    }

    // ---- epilogue: C = acc + bias ----
#pragma unroll
    for (int mt = 0; mt < 2; mt++) {
#pragma unroll
        for (int nt = 0; nt < 4; nt++) {
            const int m0 = block_m + wm * 32 + mt * 16 + g;
            const int n0 = block_n + wn * 32 + nt * 8 + t4 * 2;
            const float bv0 = bias[n0], bv1 = bias[n0 + 1];
            if (m0 < M) {
                C[(size_t)m0 * N + n0]     = acc[mt][nt][0] + bv0;
                C[(size_t)m0 * N + n0 + 1] = acc[mt][nt][1] + bv1;
            }
            if (m0 + 8 < M) {
                C[(size_t)(m0 + 8) * N + n0]     = acc[mt][nt][2] + bv0;
                C[(size_t)(m0 + 8) * N + n0 + 1] = acc[mt][nt][3] + bv1;
            }
        }
    }
}

static void run_gemm(const float* A, const float* W, const float* b, float* C,
                     int M, int N, int K)
{
    dim3 grid(N / BN, (M + BM - 1) / BM);
    gemm_tf32_kernel<<<grid, 256>>>(A, W, b, C, M, N, K);
}

// ---------------------------------------------------------------------------
// Softmax / segment machinery
// ---------------------------------------------------------------------------
__device__ __forceinline__ void atomicMaxFloat(float* addr, float val)
{
    if (val >= 0.f)
        atomicMax((int*)addr, __float_as_int(val));
    else
        atomicMin((unsigned int*)addr, __float_as_uint(val));
}

__global__ void init_pass_kernel(float* segmax, float* segsum, int* counts, int nseg)
{
    int i = blockIdx.x * blockDim.x + threadIdx.x;
    if (i < nseg) {
        segmax[i] = -INFINITY;
        segsum[i] = 0.f;
        counts[i] = 0;
    }
}

__global__ __launch_bounds__(256) void score_kernel(
    const float* __restrict__ kmat, const float* __restrict__ qmat,
    const int* __restrict__ kidx, const int* __restrict__ qidx,
    const int* __restrict__ seg,
    float* __restrict__ score, float* __restrict__ segmax, int* __restrict__ counts,
    int nnz)
{
    const int w = (blockIdx.x * blockDim.x + threadIdx.x) >> 5;
    const int lane = threadIdx.x & 31;
    if (w >= nnz) return;
    const int ki = kidx[w];
    const int qi = qidx[w];
    float4 a = *(const float4*)&kmat[(size_t)ki * QDIM + lane * 4];
    float4 b = *(const float4*)&qmat[(size_t)qi * QDIM + lane * 4];
    float d = a.x * b.x + a.y * b.y + a.z * b.z + a.w * b.w;
#pragma unroll
    for (int o = 16; o > 0; o >>= 1) d += __shfl_xor_sync(0xffffffffu, d, o);
    if (lane == 0) {
        float s = (d >= 0.f ? d : NEG_SLOPE * d) * SCORE_SCALE;
        score[w] = s;
        const int sg = seg[w];
        atomicMaxFloat(&segmax[sg], s);
        atomicAdd(&counts[sg], 1);
    }
}

// ---- two-level scan: per-block scan + partials scan + add ----
__global__ __launch_bounds__(1024) void scan_block_kernel(
    const int* __restrict__ counts, int* __restrict__ offsets,
    int* __restrict__ partials, int n)
{
    __shared__ int sh[1024];
    const int t = threadIdx.x;
    const int i = blockIdx.x * 1024 + t;
    const int x = (i < n) ? counts[i] : 0;
    sh[t] = x;
    __syncthreads();
    for (int off = 1; off < 1024; off <<= 1) {
        int v = (t >= off) ? sh[t - off] : 0;
        __syncthreads();
        sh[t] += v;
        __syncthreads();
    }
    if (i < n) offsets[i] = sh[t] - x;   // block-local exclusive
    if (t == 1023) partials[blockIdx.x] = sh[1023];
}

__global__ void scan_partials_kernel(int* partials, int* offsets, int nb, int n)
{
    __shared__ int sh[64];
    const int t = threadIdx.x;
    const int x = (t < nb) ? partials[t] : 0;
    sh[t] = x;
    __syncthreads();
    for (int off = 1; off < 64; off <<= 1) {
        int v = (t >= off) ? sh[t - off] : 0;
        __syncthreads();
        sh[t] += v;
        __syncthreads();
    }
    if (t < nb) partials[t] = sh[t] - x;  // exclusive
    if (t == 63) offsets[n] = sh[63];     // total
}

__global__ void scan_add_kernel(int* __restrict__ offsets, int* __restrict__ cursor,
                                const int* __restrict__ partials, int n)
{
    int i = blockIdx.x * blockDim.x + threadIdx.x;
    if (i < n) {
        int v = offsets[i] + partials[i >> 10];
        offsets[i] = v;
        cursor[i] = v;
    }
}

__global__ void build_perm_kernel(const int* __restrict__ seg, int* __restrict__ cursor,
                                  int* __restrict__ perm, int nnz)
{
    int i = blockIdx.x * blockDim.x + threadIdx.x;
    if (i < nnz) {
        int pos = atomicAdd(&cursor[seg[i]], 1);
        perm[pos] = i;
    }
}

__global__ void expsum_kernel(const float* __restrict__ score, const int* __restrict__ seg,
                              const float* __restrict__ segmax, float* __restrict__ expw,
                              float* __restrict__ segsum, int nnz)
{
    int i = blockIdx.x * blockDim.x + threadIdx.x;
    if (i < nnz) {
        const int sg = seg[i];
        float e = expf(score[i] - segmax[sg]);
        expw[i] = e;
        atomicAdd(&segsum[sg], e);
    }
}

__global__ __launch_bounds__(256) void aggregate_kernel(
    const float* __restrict__ vmat,
    const int* __restrict__ rowidx,
    const int* __restrict__ offsets, const int* __restrict__ perm,
    const float* __restrict__ expw, const float* __restrict__ segsum,
    float* __restrict__ out, int nseg)
{
    __shared__ int   sh_r[128];
    __shared__ float sh_w[128];
    const int s = blockIdx.x;
    if (s >= nseg) return;
    const int d = threadIdx.x;
    const int beg = offsets[s];
    const int end = offsets[s + 1];
    float acc = 0.f;
    for (int cb = beg; cb < end; cb += 128) {
        const int m = min(128, end - cb);
        if (d < m) {
            const int nz = perm[cb + d];
            sh_w[d] = expw[nz];
            sh_r[d] = rowidx[nz];
        }
        __syncthreads();
        for (int j = 0; j < m; j++)
            acc += sh_w[j] * vmat[(size_t)sh_r[j] * 256 + d];
        __syncthreads();
    }
    const float denom = fmaxf(segsum[s], 1e-20f);
    out[(size_t)s * 256 + d] = fmaxf(acc / denom, 0.f);
}

// ---------------------------------------------------------------------------
// Launch
// ---------------------------------------------------------------------------
extern "C" void kernel_launch(void* const* d_in, const int* in_sizes, int n_in,
                              void* d_out, int out_size)
{
    const float* vfeat    = (const float*)d_in[0];
    const float* efeat    = (const float*)d_in[1];
    const int*   node_idx = (const int*)d_in[2];
    const int*   edge_idx = (const int*)d_in[3];
    const float* W_vtx = (const float*)d_in[4];  const float* b_vtx = (const float*)d_in[5];
    const float* W_qe  = (const float*)d_in[6];  const float* b_qe  = (const float*)d_in[7];
    const float* W_kv  = (const float*)d_in[8];  const float* b_kv  = (const float*)d_in[9];
    const float* W_vv  = (const float*)d_in[10]; const float* b_vv  = (const float*)d_in[11];
    const float* W_qv  = (const float*)d_in[12]; const float* b_qv  = (const float*)d_in[13];
    const float* W_ke  = (const float*)d_in[14]; const float* b_ke  = (const float*)d_in[15];
    const float* W_ve  = (const float*)d_in[16]; const float* b_ve  = (const float*)d_in[17];

    float* out_v = (float*)d_out;
    float* out_e = out_v + (size_t)N_NODES * VDIM;

    float *feat_v, *k1, *v1, *q2, *q1, *k2, *v2, *score, *expw, *segmax, *segsum;
    int *counts, *offsets, *cursor, *perm, *partials;
    cudaGetSymbolAddress((void**)&feat_v, g_feat_v);
    cudaGetSymbolAddress((void**)&k1, g_k1);
    cudaGetSymbolAddress((void**)&v1, g_v1);
    cudaGetSymbolAddress((void**)&q2, g_q2);
    cudaGetSymbolAddress((void**)&q1, g_q1);
    cudaGetSymbolAddress((void**)&k2, g_k2);
    cudaGetSymbolAddress((void**)&v2, g_v2);
    cudaGetSymbolAddress((void**)&score, g_score);
    cudaGetSymbolAddress((void**)&expw, g_expw);
    cudaGetSymbolAddress((void**)&segmax, g_segmax);
    cudaGetSymbolAddress((void**)&segsum, g_segsum);
    cudaGetSymbolAddress((void**)&counts, g_counts);
    cudaGetSymbolAddress((void**)&offsets, g_offsets);
    cudaGetSymbolAddress((void**)&cursor, g_cursor);
    cudaGetSymbolAddress((void**)&perm, g_perm);
    cudaGetSymbolAddress((void**)&partials, g_partials);

    const int scoreBlocks = (NNZ * 32 + 255) / 256;
    const int nnzBlocks   = (NNZ + 255) / 256;

    // ---- projections ----
    run_gemm(vfeat,  W_vtx, b_vtx, feat_v, N_NODES, VDIM, KIN);
    run_gemm(feat_v, W_kv,  b_kv,  k1,     N_NODES, QDIM, VDIM);
    run_gemm(feat_v, W_vv,  b_vv,  v1,     N_NODES, EDIM, VDIM);
    run_gemm(feat_v, W_qv,  b_qv,  q2,     N_NODES, QDIM, VDIM);
    run_gemm(efeat,  W_qe,  b_qe,  q1,     N_EDGES, QDIM, KIN);

    // ---- pass 1: nodes -> hyperedges ----
    {
        const int nseg = N_EDGES;
        const int nb = (nseg + 1023) / 1024;
        init_pass_kernel<<<(nseg + 255) / 256, 256>>>(segmax, segsum, counts, nseg);
        score_kernel<<<scoreBlocks, 256>>>(k1, q1, node_idx, edge_idx, edge_idx,
                                           score, segmax, counts, NNZ);
        scan_block_kernel<<<nb, 1024>>>(counts, offsets, partials, nseg);
        scan_partials_kernel<<<1, 64>>>(partials, offsets, nb, nseg);
        scan_add_kernel<<<(nseg + 255) / 256, 256>>>(offsets, cursor, partials, nseg);
        build_perm_kernel<<<nnzBlocks, 256>>>(edge_idx, cursor, perm, NNZ);
        expsum_kernel<<<nnzBlocks, 256>>>(score, edge_idx, segmax, expw, segsum, NNZ);
        aggregate_kernel<<<nseg, 256>>>(v1, node_idx, offsets, perm, expw, segsum,
                                        out_e, nseg);
    }

    // ---- edge-side projections from feat_e ----
    run_gemm(out_e, W_ke, b_ke, k2, N_EDGES, QDIM, EDIM);
    run_gemm(out_e, W_ve, b_ve, v2, N_EDGES, VDIM, EDIM);

    // ---- pass 2: hyperedges -> nodes ----
    {
        const int nseg = N_NODES;
        const int nb = (nseg + 1023) / 1024;
        init_pass_kernel<<<(nseg + 255) / 256, 256>>>(segmax, segsum, counts, nseg);
        score_kernel<<<scoreBlocks, 256>>>(k2, q2, edge_idx, node_idx, node_idx,
                                           score, segmax, counts, NNZ);
        scan_block_kernel<<<nb, 1024>>>(counts, offsets, partials, nseg);
        scan_partials_kernel<<<1, 64>>>(partials, offsets, nb, nseg);
        scan_add_kernel<<<(nseg + 255) / 256, 256>>>(offsets, cursor, partials, nseg);
        build_perm_kernel<<<nnzBlocks, 256>>>(node_idx, cursor, perm, NNZ);
        expsum_kernel<<<nnzBlocks, 256>>>(score, node_idx, segmax, expw, segsum, NNZ);
        aggregate_kernel<<<nseg, 256>>>(v2, edge_idx, offsets, perm, expw, segsum,
                                        out_v, nseg);
    }
}